// round 3
// baseline (speedup 1.0000x reference)
#include <cuda_runtime.h>
#include <math_constants.h>

// Until operator: out[b,t] = tau * lse_k( min(s2[t+k], -tau*lse_{j<=k}(-s1[t+j]/tau)) / tau )
// over k = 0..127, tau = 0.01. Base-2 log domain, inputs pre-scaled by
// C = (1/tau)*log2(e) so every transcendental is a single MUFU ex2/lg2.
//
// Fast-path trick: q = -(am + lg2 as) (smooth prefix-min, scaled) changes only
// when a new significant s1 minimum arrives (x > am - 26); mm (candidate max
// anchor) changes only when a new best candidate arrives. Both are rare. With
// e2q = ex2(q - mm) cached, the per-step M contribution is EXACTLY
//   ex2(min(y,q) - mm) = min(ex2(y - mm), e2q)        (ex2 monotone)
// so the steady-state step costs 1 MUFU. Rare events are handled in a
// warp-uniform voted slow path that does the full exact update.
//
// Early exit (exact to ~2^-23 rel on ms): once q < mm - 30 for all lanes,
// every future contribution is < 2^-30 while ms >= 2^-7 -> no-ops.

#define TILE   512
#define WSTEPS 128
#define CHUNK  8

__device__ __forceinline__ float ex2f(float x) {
    float r; asm("ex2.approx.f32 %0, %1;" : "=f"(r) : "f"(x)); return r;
}
__device__ __forceinline__ float lg2f(float x) {
    float r; asm("lg2.approx.f32 %0, %1;" : "=f"(r) : "f"(x)); return r;
}

__global__ __launch_bounds__(TILE)
void until_kernel(const float* __restrict__ g1,
                  const float* __restrict__ g2,
                  float* __restrict__ out, int T) {
    __shared__ float2 sh[TILE + WSTEPS];   // {x = -C*s1, y = C*s2}

    const float C = 144.26950408889634f;  // (1/tau) * log2(e), tau = 0.01

    const int row = blockIdx.y;
    const int t0  = blockIdx.x * TILE;
    const float* r1 = g1 + (size_t)row * T;
    const float* r2 = g2 + (size_t)row * T;

    for (int i = threadIdx.x; i < TILE + WSTEPS; i += TILE) {
        int g = t0 + i;
        float2 v;
        if (g < T) {
            v.x = -C * __ldg(r1 + g);
            v.y =  C * __ldg(r2 + g);
        } else {
            v.x = -1e30f;   // no contribution to A (exp -> 0)
            v.y = -1e30f;   // cand -> -1e30, no contribution to M
        }
        sh[i] = v;
    }
    __syncthreads();

    const int i = threadIdx.x;

    // A state: anchor am, scaled sum as, q = -(am + lg2 as), threshold for
    // "this x matters". M state: anchor mm (running max cand), sum ms,
    // cached e2q = ex2(q - mm).
    // Init so that step k=0 is forced down the slow path (thr = -3e38 < any x).
    float am = -1e38f, as = 0.0f, q = 1e38f, thr = -3.0e38f;
    float mm = -1e38f, ms = 0.0f, e2q = 0.0f;

    #pragma unroll 1
    for (int kb = 0; kb < WSTEPS; kb += CHUNK) {
        #pragma unroll
        for (int u = 0; u < CHUNK; ++u) {
            float2 v = sh[i + kb + u];
            float x = v.x;                    // -C * s1[t+k]
            float y = v.y;                    //  C * s2[t+k]

            bool  pa  = (x > thr);            // new significant s1-min
            float e2y = ex2f(y - mm);
            float e2  = fminf(e2y, e2q);      // = ex2(min(y,q) - mm), exact

            if (__any_sync(0xffffffffu, pa || (e2 > 1.0f))) {
                // Slow path (warp-uniform entry; per-lane exact fixups).
                if (pa) {
                    float d = x - am;
                    float e = ex2f(-fabsf(d));
                    as = (d > 0.0f) ? fmaf(as, e, 1.0f) : (as + e);
                    am = fmaxf(am, x);
                    thr = am - 26.0f;
                    q = -(am + lg2f(as));
                }
                float cand = fminf(y, q);
                if (cand > mm) {
                    ms = fmaf(ms, ex2f(mm - cand), 1.0f);  // rescale + new max term
                    mm = cand;
                } else {
                    ms += ex2f(cand - mm);
                }
                e2q = ex2f(q - mm);
            } else {
                ms += e2;                      // 1-MUFU steady state
            }
        }
        // Exit: all future contributions are fp32 no-ops for every lane.
        if (__all_sync(0xffffffffu, q < mm - 30.0f)) break;
    }

    // out = tau * M_natural = (mm + log2(ms)) * tau * ln(2)
    out[(size_t)row * T + t0 + i] = (mm + lg2f(ms)) * 0.006931471805599453f;
}

extern "C" void kernel_launch(void* const* d_in, const int* in_sizes, int n_in,
                              void* d_out, int out_size) {
    const float* s1 = (const float*)d_in[0];
    const float* s2 = (const float*)d_in[1];
    float* out = (float*)d_out;

    const int T = 16384;
    const int B = out_size / T;   // 512

    dim3 grid(T / TILE, B);       // (32, 512)
    until_kernel<<<grid, TILE>>>(s1, s2, out, T);
}

// round 4
// speedup vs baseline: 1.8092x; 1.8092x over previous
#include <cuda_runtime.h>
#include <math_constants.h>

// Until operator: out[b,t] = tau * lse_k( min(s2[t+k], -tau*lse_{j<=k}(-s1[t+j]/tau)) / tau )
// over k = 0..127, tau = 0.01. Base-2 log domain, inputs pre-scaled by
// C = (1/tau)*log2(e) so transcendentals are single ops.
//
// Per-step MUFU reduced 3 -> 1:
//  - as-update uses Schraudolph bit-trick exp2 (err ~±3%; q sensitivity gives
//    ~±3e-4 output error worst case, vs 1e-3 tolerance)
//  - q uses bit-trick log2 (err ~±0.043 log2 -> ±3e-4 output)
//  - the M contribution ex2 (directly in the output sum) stays exact MUFU.
//
// Early exit threshold relaxed to 13: once q < mm-13 on all lanes, remaining
// contributions sum to < 128*2^-13 -> output error < tau*0.0156 = 1.6e-4.

#define TILE   512
#define WSTEPS 128
#define CHUNK  8

__device__ __forceinline__ float ex2f(float x) {
    float r; asm("ex2.approx.f32 %0, %1;" : "=f"(r) : "f"(x)); return r;
}
__device__ __forceinline__ float lg2f(float x) {
    float r; asm("lg2.approx.f32 %0, %1;" : "=f"(r) : "f"(x)); return r;
}

// approx 2^z for z <= 0, centered rel err ~±3%. 3 ops, FMA/ALU pipes only.
__device__ __forceinline__ float fex2(float z) {
    z = fmaxf(z, -126.0f);
    // bits = z*2^23 + (127 - 0.0434609)*2^23
    return __int_as_float(__float2int_rn(fmaf(z, 8388608.0f, 1064988634.0f)));
}

// approx log2(s) for s > 0, centered err ~±0.043. 2 ops.
__device__ __forceinline__ float flg2(float s) {
    return fmaf((float)__float_as_int(s), 1.1920929e-7f, -126.9565392f);
}

__global__ __launch_bounds__(TILE)
void until_kernel(const float* __restrict__ g1,
                  const float* __restrict__ g2,
                  float* __restrict__ out, int T) {
    __shared__ float2 sh[TILE + WSTEPS];   // {x = -C*s1, y = C*s2}

    const float C = 144.26950408889634f;  // (1/tau) * log2(e), tau = 0.01

    const int row = blockIdx.y;
    const int t0  = blockIdx.x * TILE;
    const float* r1 = g1 + (size_t)row * T;
    const float* r2 = g2 + (size_t)row * T;

    for (int i = threadIdx.x; i < TILE + WSTEPS; i += TILE) {
        int g = t0 + i;
        float2 v;
        if (g < T) {
            v.x = -C * __ldg(r1 + g);
            v.y =  C * __ldg(r2 + g);
        } else {
            v.x = -1e30f;   // no contribution to A (exp -> 0)
            v.y = -1e30f;   // cand -> -1e30, no contribution to M
        }
        sh[i] = v;
    }
    __syncthreads();

    const int i = threadIdx.x;

    // Online logsumexp state (base-2): A for smooth-min over s1, M for smooth-max.
    float am = -1e38f, as = 0.0f;
    float mm = -1e38f, ms = 0.0f;
    float qv = CUDART_INF_F;

    #pragma unroll 1
    for (int kb = 0; kb < WSTEPS; kb += CHUNK) {
        #pragma unroll
        for (int u = 0; u < CHUNK; ++u) {
            float2 v = sh[i + kb + u];
            float x = v.x;                   // -C * s1[t+k]
            float y = v.y;                   //  C * s2[t+k]

            // A <- logaddexp2(A, x): bit-trick exp2 (error-tolerant path)
            float d = x - am;
            float e = fex2(-fabsf(d));
            as = (d > 0.0f) ? fmaf(as, e, 1.0f) : (as + e);
            am = fmaxf(am, x);

            // q = C*smooth_min so far (bit-trick log2); cand = min(C*s2, q)
            qv = -(am + flg2(as));
            float cand = fminf(y, qv);

            // M <- logaddexp2(M, cand): exact MUFU (feeds output directly)
            float d2 = cand - mm;
            float e2 = ex2f(-fabsf(d2));
            ms = (d2 > 0.0f) ? fmaf(ms, e2, 1.0f) : (ms + e2);
            mm = fmaxf(mm, cand);
        }
        // Exit: remaining contributions sum below 128*2^-13 -> < 1.6e-4 on out.
        if (__all_sync(0xffffffffu, qv < mm - 13.0f)) break;
    }

    // out = tau * M_natural = (mm + log2(ms)) * tau * ln(2)
    out[(size_t)row * T + t0 + i] = (mm + lg2f(ms)) * 0.006931471805599453f;
}

extern "C" void kernel_launch(void* const* d_in, const int* in_sizes, int n_in,
                              void* d_out, int out_size) {
    const float* s1 = (const float*)d_in[0];
    const float* s2 = (const float*)d_in[1];
    float* out = (float*)d_out;

    const int T = 16384;
    const int B = out_size / T;   // 512

    dim3 grid(T / TILE, B);       // (32, 512)
    until_kernel<<<grid, TILE>>>(s1, s2, out, T);
}

// round 5
// speedup vs baseline: 1.9412x; 1.0730x over previous
#include <cuda_runtime.h>
#include <math_constants.h>

// Until operator: out[b,t] = tau * lse_k( min(s2[t+k], -tau*lse_{j<=k}(-s1[t+j]/tau)) / tau )
// over k = 0..127, tau = 0.01. Base-2 log domain, inputs pre-scaled by
// C = (1/tau)*log2(e).
//
// - A-side (smooth prefix-min of s1): online LSE with Schraudolph bit-trick exp2
//   (error-tolerant: q sensitivity gives <= ~3e-4 output error). The underflow
//   clamp is FREE via float->uint32 saturation (negative -> 0 -> +0.0f).
// - q via bit-trick log2 (+-0.043 log2 -> +-3e-4 output).
// - M-side contribution ex2 stays exact MUFU (feeds output directly).
// - Exit: tail error = tau * 121 * 2^(q-mm) / ms. Exit when q < mm - 13 + log2(ms)
//   (ms >= 1 always); same 1.5e-4 bound as before but not conservative by log2(ms).

#define TILE   128
#define WSTEPS 128
#define CHUNK  8

__device__ __forceinline__ float ex2f(float x) {
    float r; asm("ex2.approx.f32 %0, %1;" : "=f"(r) : "f"(x)); return r;
}
__device__ __forceinline__ float lg2f(float x) {
    float r; asm("lg2.approx.f32 %0, %1;" : "=f"(r) : "f"(x)); return r;
}

// approx 2^z for z <= 0, centered rel err ~±3%. FFMA + F2I.U32 (saturating
// negative -> 0 gives the underflow clamp for free).
__device__ __forceinline__ float fex2(float z) {
    return __uint_as_float(__float2uint_rn(fmaf(z, 8388608.0f, 1064988634.0f)));
}

__global__ __launch_bounds__(TILE)
void until_kernel(const float* __restrict__ g1,
                  const float* __restrict__ g2,
                  float* __restrict__ out, int T) {
    __shared__ float2 sh[TILE + WSTEPS];   // {x = -C*s1, y = C*s2}

    const float C = 144.26950408889634f;  // (1/tau) * log2(e), tau = 0.01

    const int row = blockIdx.y;
    const int t0  = blockIdx.x * TILE;
    const float* r1 = g1 + (size_t)row * T;
    const float* r2 = g2 + (size_t)row * T;

    #pragma unroll
    for (int i = threadIdx.x; i < TILE + WSTEPS; i += TILE) {
        int g = t0 + i;
        float2 v;
        if (g < T) {
            v.x = -C * __ldg(r1 + g);
            v.y =  C * __ldg(r2 + g);
        } else {
            v.x = -1e30f;   // no contribution to A (exp -> 0)
            v.y = -1e30f;   // cand -> -1e30, no contribution to M
        }
        sh[i] = v;
    }
    __syncthreads();

    const float2* __restrict__ p = sh + threadIdx.x;

    // Online logsumexp state (base-2): A (smooth-min of s1), M (smooth-max of cands).
    float am = -1e38f, as = 0.0f;
    float mm = -1e38f, ms = 0.0f;
    float qv = CUDART_INF_F;

    #pragma unroll 1
    for (int kb = 0; kb < WSTEPS; kb += CHUNK) {
        #pragma unroll
        for (int u = 0; u < CHUNK; ++u) {
            float2 v = p[u];
            float x = v.x;                   // -C * s1[t+k]
            float y = v.y;                   //  C * s2[t+k]

            // A <- logaddexp2(A, x)
            float d = x - am;
            float e = fex2(fminf(d, -d));    // 2^{-|d|} with free underflow clamp
            as = (d > 0.0f) ? fmaf(as, e, 1.0f) : (as + e);
            am = fmaxf(am, x);

            // q = C*smooth_min so far (bit-trick log2); cand = min(C*s2, q)
            qv = -fmaf((float)__float_as_int(as), 1.1920929e-7f, -126.9565392f) - am;
            float cand = fminf(y, qv);

            // M <- logaddexp2(M, cand): exact MUFU
            float d2 = cand - mm;
            float e2 = ex2f(0.0f - fabsf(d2));
            ms = (d2 > 0.0f) ? fmaf(ms, e2, 1.0f) : (ms + e2);
            mm = fmaxf(mm, cand);
        }
        p += CHUNK;
        // Exit when tail bound tau*121*2^(qv-mm)/ms < 1.5e-4:
        //   qv < mm + (log2(ms) - 13);  log2(ms) via bit trick, -13 folded in.
        float lt = fmaf((float)__float_as_int(ms), 1.1920929e-7f, -139.9565392f);
        if (__all_sync(0xffffffffu, qv < mm + lt)) break;
    }

    // out = tau * M_natural = (mm + log2(ms)) * tau * ln(2)
    out[(size_t)row * T + t0 + threadIdx.x] = (mm + lg2f(ms)) * 0.006931471805599453f;
}

extern "C" void kernel_launch(void* const* d_in, const int* in_sizes, int n_in,
                              void* d_out, int out_size) {
    const float* s1 = (const float*)d_in[0];
    const float* s2 = (const float*)d_in[1];
    float* out = (float*)d_out;

    const int T = 16384;
    const int B = out_size / T;   // 512

    dim3 grid(T / TILE, B);       // (128, 512)
    until_kernel<<<grid, TILE>>>(s1, s2, out, T);
}